// round 9
// baseline (speedup 1.0000x reference)
#include <cuda_runtime.h>
#include <cuda_fp16.h>
#include <cstdint>

#define T_LEN 1024
#define NTH   512
#define HSTR  136        // halves per row (272 B = 17*16B): 16B-aligned, conflict-free

static __device__ __forceinline__ float fsig(float x) {
    return __fdividef(1.0f, 1.0f + __expf(-x));
}
static __device__ __forceinline__ float ftanh(float x) {
    return fmaf(-2.0f, __fdividef(1.0f, __expf(2.0f * x) + 1.0f), 1.0f);
}
static __device__ __forceinline__ uint32_t pack2(__half a, __half b) {
    __half2 t = __halves2half2(a, b);
    return *(uint32_t*)&t;
}
static __device__ __forceinline__ __half wsplit(float w, bool lo) {
    __half h = __float2half_rn(w);
    return lo ? __float2half_rn(w - __half2float(h)) : h;
}
static __device__ __forceinline__ void mma16816(float* d, const uint32_t* a, const uint32_t* b) {
    asm volatile(
        "mma.sync.aligned.m16n8k16.row.col.f32.f16.f16.f32 "
        "{%0,%1,%2,%3}, {%4,%5,%6,%7}, {%8,%9}, {%0,%1,%2,%3};"
        : "+f"(d[0]), "+f"(d[1]), "+f"(d[2]), "+f"(d[3])
        : "r"(a[0]), "r"(a[1]), "r"(a[2]), "r"(a[3]), "r"(b[0]), "r"(b[1]));
}

__global__ void out_init(float* out, const float* fc_b, int n) {
    int i = blockIdx.x * blockDim.x + threadIdx.x;
    if (i < n) out[i] = fc_b[0];
}

__global__ __launch_bounds__(NTH, 1)
void bilstm_mma(const float* __restrict__ x,
                const float* __restrict__ Wih_f, const float* __restrict__ Whh_f,
                const float* __restrict__ bih_f, const float* __restrict__ bhh_f,
                const float* __restrict__ Wih_b, const float* __restrict__ Whh_b,
                const float* __restrict__ bih_b, const float* __restrict__ bhh_b,
                const float* __restrict__ fc_w, float* __restrict__ out)
{
    __shared__ __align__(16) __half hs[2][16][HSTR];   // h in A-fragment-permuted order
    __shared__ float psum[2][16][16];

    const int tid = threadIdx.x, wid = tid >> 5, lane = tid & 31;
    const int q = lane & 3, r = lane >> 2;             // q: frag thread-in-group, r: stream/group
    const int dir = blockIdx.x & 1;
    const int b0 = (blockIdx.x >> 1) * 16;

    const float* Whh = dir ? Whh_b : Whh_f;
    const float* Wih = dir ? Wih_b : Wih_f;
    const float* bih = dir ? bih_b : bih_f;
    const float* bhh = dir ? bhh_b : bhh_f;

    for (int i = tid; i < 2 * 16 * HSTR; i += NTH) (&hs[0][0][0])[i] = __float2half(0.f);

    // ---- B fragments: warp owns units 4*wid..4*wid+3; nt0 = i/g rows, nt1 = f/o rows ----
    uint32_t bf[8][2][2];
    {
        const int qp = r >> 1, odd = r & 1;
        const int unit = 4 * wid + qp;
        #pragma unroll
        for (int nt = 0; nt < 2; ++nt) {
            const int row = (nt == 0) ? (odd ? 128 + unit : unit)
                                      : (odd ? 192 + unit : 64 + unit);
            const float* wr = Whh + row * 64;
            #pragma unroll
            for (int ks = 0; ks < 8; ++ks) {
                const bool lo = ks >= 4;
                const int base = (lo ? (ks - 4) : ks) * 16 + q * 2;
                bf[ks][nt][0] = pack2(wsplit(__ldg(wr + base),     lo),
                                      wsplit(__ldg(wr + base + 1), lo));
                bf[ks][nt][1] = pack2(wsplit(__ldg(wr + base + 8), lo),
                                      wsplit(__ldg(wr + base + 9), lo));
            }
        }
    }

    // gate-owner: unit uu, streams r and r+8
    const int uu = 4 * wid + q;
    const float wi_i = Wih[uu], wi_f = Wih[64 + uu], wi_g = Wih[128 + uu], wi_o = Wih[192 + uu];
    const float bi = bih[uu] + bhh[uu],             bfc = bih[64 + uu] + bhh[64 + uu];
    const float bg = bih[128 + uu] + bhh[128 + uu], bo = bih[192 + uu] + bhh[192 + uu];
    const float fcw = fc_w[dir * 64 + uu];

    // permuted store positions: old col c -> t*32 + (c>>4)*4 + e
    const int w15 = uu & 15;
    const int nc_hi = ((w15 & 7) >> 1) * 32 + (uu >> 4) * 4 + ((w15 & 1) + ((w15 >> 3) & 1) * 2);
    const int nc_lo = nc_hi + 16;                      // lo block: jj += 4 -> +16 new cols

    float cc[2] = {0.f, 0.f};
    __syncthreads();

    const int amap[12] = {0,1,2,3, 0,1,2,3, 4,5,6,7};
    const int bmap[12] = {0,1,2,3, 4,5,6,7, 0,1,2,3};

    for (int t = 0; t < T_LEN; ++t) {
        // flush previous step's fc partials
        if (t > 0 && wid == 0 && lane < 16) {
            const float* ps = &psum[(t - 1) & 1][lane][0];
            float s = 0.f;
            #pragma unroll
            for (int j = 0; j < 16; ++j) s += ps[j];
            atomicAdd(out + (size_t)(b0 + lane) * T_LEN + (t - 1), s);
        }

        // ---- A fragments: 8x LDS.128 from permuted buffer ----
        const __half* hb = &hs[(t & 1) ^ 1][0][0];
        uint32_t af[8][4];
        {
            const uint4* p0 = (const uint4*)(hb + r * HSTR + q * 32);
            const uint4* p1 = (const uint4*)(hb + (r + 8) * HSTR + q * 32);
            #pragma unroll
            for (int m = 0; m < 4; ++m) {
                const uint4 v = p0[m];
                af[2*m][0] = v.x; af[2*m][2] = v.y; af[2*m+1][0] = v.z; af[2*m+1][2] = v.w;
                const uint4 u = p1[m];
                af[2*m][1] = u.x; af[2*m][3] = u.y; af[2*m+1][1] = u.z; af[2*m+1][3] = u.w;
            }
        }

        // ---- 24 HMMA ----
        float d[2][4] = {{0.f,0.f,0.f,0.f},{0.f,0.f,0.f,0.f}};
        #pragma unroll
        for (int ks = 0; ks < 12; ++ks) {
            mma16816(d[0], af[amap[ks]], bf[bmap[ks]][0]);
            mma16816(d[1], af[amap[ks]], bf[bmap[ks]][1]);
        }

        // ---- gates (thread-local) ----
        const int xt = dir ? (T_LEN - 1 - t) : t;
        const float xv0 = __ldg(x + (size_t)(b0 + r) * T_LEN + xt);
        const float xv1 = __ldg(x + (size_t)(b0 + r + 8) * T_LEN + xt);

        float hval[2];
        #pragma unroll
        for (int cidx = 0; cidx < 2; ++cidx) {
            const int co = cidx * 2;
            const float xv = cidx ? xv1 : xv0;
            const float zi = d[0][co]     + fmaf(xv, wi_i, bi);
            const float zg = d[0][co + 1] + fmaf(xv, wi_g, bg);
            const float zf = d[1][co]     + fmaf(xv, wi_f, bfc);
            const float zo = d[1][co + 1] + fmaf(xv, wi_o, bo);
            cc[cidx] = fmaf(fsig(zf), cc[cidx], fsig(zi) * ftanh(zg));
            hval[cidx] = fsig(zo) * ftanh(cc[cidx]);
        }

        // ---- store h(t) hi/lo at permuted positions ----
        __half* hw = &hs[t & 1][0][0];
        #pragma unroll
        for (int cidx = 0; cidx < 2; ++cidx) {
            const int s = cidx ? (r + 8) : r;
            const __half hh = __float2half_rn(hval[cidx]);
            const __half hl = __float2half_rn(hval[cidx] - __half2float(hh));
            hw[s * HSTR + nc_hi] = hh;
            hw[s * HSTR + nc_lo] = hl;
        }

        // ---- fc partials: reduce the 4 units of this warp ----
        float p0 = fcw * hval[0], p1 = fcw * hval[1];
        p0 += __shfl_xor_sync(0xffffffffu, p0, 1);
        p0 += __shfl_xor_sync(0xffffffffu, p0, 2);
        p1 += __shfl_xor_sync(0xffffffffu, p1, 1);
        p1 += __shfl_xor_sync(0xffffffffu, p1, 2);
        if (q == 0) {
            psum[t & 1][r][wid] = p0;
            psum[t & 1][r + 8][wid] = p1;
        }
        __syncthreads();
    }

    // final flush
    if (wid == 0 && lane < 16) {
        const float* ps = &psum[(T_LEN - 1) & 1][lane][0];
        float s = 0.f;
        #pragma unroll
        for (int j = 0; j < 16; ++j) s += ps[j];
        atomicAdd(out + (size_t)(b0 + lane) * T_LEN + (T_LEN - 1), s);
    }
}

extern "C" void kernel_launch(void* const* d_in, const int* in_sizes, int n_in,
                              void* d_out, int out_size) {
    const float* x     = (const float*)d_in[0];
    const float* Wih_f = (const float*)d_in[1];
    const float* Whh_f = (const float*)d_in[2];
    const float* bih_f = (const float*)d_in[3];
    const float* bhh_f = (const float*)d_in[4];
    const float* Wih_b = (const float*)d_in[5];
    const float* Whh_b = (const float*)d_in[6];
    const float* bih_b = (const float*)d_in[7];
    const float* bhh_b = (const float*)d_in[8];
    const float* fc_w  = (const float*)d_in[9];
    const float* fc_b  = (const float*)d_in[10];
    float* out = (float*)d_out;

    out_init<<<(out_size + 255) / 256, 256>>>(out, fc_b, out_size);

    const int B = in_sizes[0] / T_LEN;   // 1024
    const int grid = (B / 16) * 2;       // 128 CTAs: (batch-group, direction)
    bilstm_mma<<<grid, NTH>>>(x, Wih_f, Whh_f, bih_f, bhh_f,
                              Wih_b, Whh_b, bih_b, bhh_b, fc_w, out);
    (void)n_in;
}

// round 10
// speedup vs baseline: 1.3539x; 1.3539x over previous
#include <cuda_runtime.h>
#include <cuda_fp16.h>
#include <cstdint>

#define T_LEN 1024
#define NTH   256
#define HSTR  136        // halves per row (272 B, 16B-aligned, conflict-free)

static __device__ __forceinline__ float tanhapx(float x) {
    float y;
    asm("tanh.approx.f32 %0, %1;" : "=f"(y) : "f"(x));
    return y;
}
static __device__ __forceinline__ float fsig(float x) {
    return fmaf(0.5f, tanhapx(0.5f * x), 0.5f);
}
static __device__ __forceinline__ float ftanh(float x) {
    return tanhapx(x);
}
static __device__ __forceinline__ uint32_t pack2(__half a, __half b) {
    __half2 t = __halves2half2(a, b);
    return *(uint32_t*)&t;
}
static __device__ __forceinline__ __half wsplit(float w, bool lo) {
    __half h = __float2half_rn(w);
    return lo ? __float2half_rn(w - __half2float(h)) : h;
}
// column permutation for the vectorized A-fragment buffer (validated in R8)
static __device__ __forceinline__ int perm(int c) {
    return (((c & 7) >> 1) << 5) + ((c >> 4) << 2) + (c & 1) + (((c >> 3) & 1) << 1);
}
static __device__ __forceinline__ void mma16816(float* d, const uint32_t* a, const uint32_t* b) {
    asm volatile(
        "mma.sync.aligned.m16n8k16.row.col.f32.f16.f16.f32 "
        "{%0,%1,%2,%3}, {%4,%5,%6,%7}, {%8,%9}, {%0,%1,%2,%3};"
        : "+f"(d[0]), "+f"(d[1]), "+f"(d[2]), "+f"(d[3])
        : "r"(a[0]), "r"(a[1]), "r"(a[2]), "r"(a[3]), "r"(b[0]), "r"(b[1]));
}

__global__ void out_init(float* out, const float* fc_b, int n) {
    int i = blockIdx.x * blockDim.x + threadIdx.x;
    if (i < n) out[i] = fc_b[0];
}

__global__ __launch_bounds__(NTH, 1)
void bilstm_mma(const float* __restrict__ x,
                const float* __restrict__ Wih_f, const float* __restrict__ Whh_f,
                const float* __restrict__ bih_f, const float* __restrict__ bhh_f,
                const float* __restrict__ Wih_b, const float* __restrict__ Whh_b,
                const float* __restrict__ bih_b, const float* __restrict__ bhh_b,
                const float* __restrict__ fc_w, float* __restrict__ out)
{
    __shared__ __align__(16) __half hs[2][16][HSTR];   // h (hi/lo) in A-fragment-permuted order
    __shared__ float psum[2][16][8];

    const int tid = threadIdx.x, wid = tid >> 5, lane = tid & 31;
    const int q = lane & 3, r = lane >> 2;
    const int dir = blockIdx.x & 1;
    const int b0 = (blockIdx.x >> 1) * 16;

    const float* Whh = dir ? Whh_b : Whh_f;
    const float* Wih = dir ? Wih_b : Wih_f;
    const float* bih = dir ? bih_b : bih_f;
    const float* bhh = dir ? bhh_b : bhh_f;

    for (int i = tid; i < 2 * 16 * HSTR; i += NTH) (&hs[0][0][0])[i] = __float2half(0.f);

    // ---- B fragments (Whh^T), hi/lo K-extension: bf[ks 0..7][nt 0..3][2] ----
    uint32_t bf[8][4][2];
    {
        const int qp = r >> 1, odd = r & 1;
        #pragma unroll
        for (int nt = 0; nt < 4; ++nt) {
            const int unit = 8 * wid + (nt >= 2 ? 4 : 0) + qp;
            const int row = ((nt & 1) ? (odd ? 192 : 64) : (odd ? 128 : 0)) + unit;
            const float* wr = Whh + row * 64;
            #pragma unroll
            for (int ks = 0; ks < 8; ++ks) {
                const bool lo = ks >= 4;
                const int wcol = (lo ? (ks - 4) : ks) * 16 + q * 2;
                bf[ks][nt][0] = pack2(wsplit(__ldg(wr + wcol),     lo),
                                      wsplit(__ldg(wr + wcol + 1), lo));
                bf[ks][nt][1] = pack2(wsplit(__ldg(wr + wcol + 8), lo),
                                      wsplit(__ldg(wr + wcol + 9), lo));
            }
        }
    }

    // gate-owner: units u1 = 8*wid+q, u2 = u1+4; streams r, r+8
    const int u1 = 8 * wid + q, u2 = u1 + 4;
    const float wi_i1 = Wih[u1], wi_f1 = Wih[64 + u1], wi_g1 = Wih[128 + u1], wi_o1 = Wih[192 + u1];
    const float wi_i2 = Wih[u2], wi_f2 = Wih[64 + u2], wi_g2 = Wih[128 + u2], wi_o2 = Wih[192 + u2];
    const float bi1 = bih[u1] + bhh[u1],             bf1 = bih[64 + u1] + bhh[64 + u1];
    const float bg1 = bih[128 + u1] + bhh[128 + u1], bo1 = bih[192 + u1] + bhh[192 + u1];
    const float bi2 = bih[u2] + bhh[u2],             bf2 = bih[64 + u2] + bhh[64 + u2];
    const float bg2 = bih[128 + u2] + bhh[128 + u2], bo2 = bih[192 + u2] + bhh[192 + u2];
    const float fcw1 = fc_w[dir * 64 + u1], fcw2 = fc_w[dir * 64 + u2];

    // permuted store columns (hi at perm(u), lo at perm(u)+16)
    const int pc1 = perm(u1), pc2 = perm(u2);

    float cc[4] = {0.f, 0.f, 0.f, 0.f};
    __syncthreads();

    const int amap[12] = {0,1,2,3, 0,1,2,3, 4,5,6,7};
    const int bmap[12] = {0,1,2,3, 4,5,6,7, 0,1,2,3};

    for (int t = 0; t < T_LEN; ++t) {
        // flush previous step's fc partials
        if (t > 0 && wid == 0 && lane < 16) {
            const float* ps = &psum[(t - 1) & 1][lane][0];
            float s = 0.f;
            #pragma unroll
            for (int j = 0; j < 8; ++j) s += ps[j];
            atomicAdd(out + (size_t)(b0 + lane) * T_LEN + (t - 1), s);
        }

        // ---- A fragments: 8x LDS.128 from permuted buffer ----
        const __half* hb = &hs[(t & 1) ^ 1][0][0];
        uint32_t af[8][4];
        {
            const uint4* p0 = (const uint4*)(hb + r * HSTR + q * 32);
            const uint4* p1 = (const uint4*)(hb + (r + 8) * HSTR + q * 32);
            #pragma unroll
            for (int m = 0; m < 4; ++m) {
                const uint4 v = p0[m];
                af[2*m][0] = v.x; af[2*m][2] = v.y; af[2*m+1][0] = v.z; af[2*m+1][2] = v.w;
                const uint4 u = p1[m];
                af[2*m][1] = u.x; af[2*m][3] = u.y; af[2*m+1][1] = u.z; af[2*m+1][3] = u.w;
            }
        }

        // ---- 48 HMMA ----
        float d[4][4] = {{0.f,0.f,0.f,0.f},{0.f,0.f,0.f,0.f},{0.f,0.f,0.f,0.f},{0.f,0.f,0.f,0.f}};
        #pragma unroll
        for (int nt = 0; nt < 4; ++nt)
            #pragma unroll
            for (int ks = 0; ks < 12; ++ks)
                mma16816(d[nt], af[amap[ks]], bf[bmap[ks]][nt]);

        // ---- gates (thread-local, tanh.approx) ----
        const int xt = dir ? (T_LEN - 1 - t) : t;
        const float xv0 = __ldg(x + (size_t)(b0 + r) * T_LEN + xt);
        const float xv1 = __ldg(x + (size_t)(b0 + r + 8) * T_LEN + xt);

        float hval[4];
        #pragma unroll
        for (int cidx = 0; cidx < 4; ++cidx) {
            const int ti = (cidx >= 2) ? 2 : 0;
            const int co = (cidx & 1) ? 2 : 0;
            const float xv = (cidx & 1) ? xv1 : xv0;
            const bool isU2 = cidx >= 2;
            const float zi = d[ti][co]     + fmaf(xv, isU2 ? wi_i2 : wi_i1, isU2 ? bi2 : bi1);
            const float zg = d[ti][co + 1] + fmaf(xv, isU2 ? wi_g2 : wi_g1, isU2 ? bg2 : bg1);
            const float zf = d[ti + 1][co]     + fmaf(xv, isU2 ? wi_f2 : wi_f1, isU2 ? bf2 : bf1);
            const float zo = d[ti + 1][co + 1] + fmaf(xv, isU2 ? wi_o2 : wi_o1, isU2 ? bo2 : bo1);
            cc[cidx] = fmaf(fsig(zf), cc[cidx], fsig(zi) * ftanh(zg));
            hval[cidx] = fsig(zo) * ftanh(cc[cidx]);
        }

        // ---- store h(t) hi/lo at permuted positions ----
        __half* hw = &hs[t & 1][0][0];
        #pragma unroll
        for (int cidx = 0; cidx < 4; ++cidx) {
            const int ss = (cidx & 1) ? (r + 8) : r;
            const int pc = (cidx >= 2) ? pc2 : pc1;
            const __half hh = __float2half_rn(hval[cidx]);
            const __half hl = __float2half_rn(hval[cidx] - __half2float(hh));
            hw[ss * HSTR + pc] = hh;
            hw[ss * HSTR + pc + 16] = hl;
        }

        // ---- fc partials ----
        float pr  = fcw1 * hval[0] + fcw2 * hval[2];
        float pr8 = fcw1 * hval[1] + fcw2 * hval[3];
        pr  += __shfl_xor_sync(0xffffffffu, pr, 1);
        pr  += __shfl_xor_sync(0xffffffffu, pr, 2);
        pr8 += __shfl_xor_sync(0xffffffffu, pr8, 1);
        pr8 += __shfl_xor_sync(0xffffffffu, pr8, 2);
        if (q == 0) {
            psum[t & 1][r][wid] = pr;
            psum[t & 1][r + 8][wid] = pr8;
        }
        __syncthreads();
    }

    // final flush
    if (wid == 0 && lane < 16) {
        const float* ps = &psum[(T_LEN - 1) & 1][lane][0];
        float s = 0.f;
        #pragma unroll
        for (int j = 0; j < 8; ++j) s += ps[j];
        atomicAdd(out + (size_t)(b0 + lane) * T_LEN + (T_LEN - 1), s);
    }
}

extern "C" void kernel_launch(void* const* d_in, const int* in_sizes, int n_in,
                              void* d_out, int out_size) {
    const float* x     = (const float*)d_in[0];
    const float* Wih_f = (const float*)d_in[1];
    const float* Whh_f = (const float*)d_in[2];
    const float* bih_f = (const float*)d_in[3];
    const float* bhh_f = (const float*)d_in[4];
    const float* Wih_b = (const float*)d_in[5];
    const float* Whh_b = (const float*)d_in[6];
    const float* bih_b = (const float*)d_in[7];
    const float* bhh_b = (const float*)d_in[8];
    const float* fc_w  = (const float*)d_in[9];
    const float* fc_b  = (const float*)d_in[10];
    float* out = (float*)d_out;

    out_init<<<(out_size + 255) / 256, 256>>>(out, fc_b, out_size);

    const int B = in_sizes[0] / T_LEN;   // 1024
    const int grid = (B / 16) * 2;       // 128 CTAs: (batch-group, direction)
    bilstm_mma<<<grid, NTH>>>(x, Wih_f, Whh_f, bih_f, bhh_f,
                              Wih_b, Whh_b, bih_b, bhh_b, fc_w, out);
    (void)n_in;
}

// round 11
// speedup vs baseline: 1.8183x; 1.3430x over previous
#include <cuda_runtime.h>
#include <cuda_fp16.h>
#include <cstdint>

#define T_LEN 1024
#define NTH   256
#define HSTR  72         // halves per row (144 B = 9*16B): 16B-aligned, conflict-free

static __device__ __forceinline__ float tanhapx(float x) {
    float y;
    asm("tanh.approx.f32 %0, %1;" : "=f"(y) : "f"(x));
    return y;
}
static __device__ __forceinline__ float fsig(float x) {
    return fmaf(0.5f, tanhapx(0.5f * x), 0.5f);
}
static __device__ __forceinline__ uint32_t pack2(__half a, __half b) {
    __half2 t = __halves2half2(a, b);
    return *(uint32_t*)&t;
}
static __device__ __forceinline__ __half wsplit(float w, bool lo) {
    __half h = __float2half_rn(w);
    return lo ? __float2half_rn(w - __half2float(h)) : h;
}
// 64-col permutation: h col c -> fragment-vectorized position
static __device__ __forceinline__ int perm64(int c) {
    return (((c & 7) >> 1) << 4) + ((c >> 4) << 2) + (((c >> 3) & 1) << 1) + (c & 1);
}
static __device__ __forceinline__ void mma16816(float* d, const uint32_t* a, const uint32_t* b) {
    asm volatile(
        "mma.sync.aligned.m16n8k16.row.col.f32.f16.f16.f32 "
        "{%0,%1,%2,%3}, {%4,%5,%6,%7}, {%8,%9}, {%0,%1,%2,%3};"
        : "+f"(d[0]), "+f"(d[1]), "+f"(d[2]), "+f"(d[3])
        : "r"(a[0]), "r"(a[1]), "r"(a[2]), "r"(a[3]), "r"(b[0]), "r"(b[1]));
}

__global__ void out_init(float* out, const float* fc_b, int n) {
    int i = blockIdx.x * blockDim.x + threadIdx.x;
    if (i < n) out[i] = fc_b[0];
}

__global__ __launch_bounds__(NTH, 1)
void bilstm_mma(const float* __restrict__ x,
                const float* __restrict__ Wih_f, const float* __restrict__ Whh_f,
                const float* __restrict__ bih_f, const float* __restrict__ bhh_f,
                const float* __restrict__ Wih_b, const float* __restrict__ Whh_b,
                const float* __restrict__ bih_b, const float* __restrict__ bhh_b,
                const float* __restrict__ fc_w, float* __restrict__ out)
{
    __shared__ __align__(16) __half hs[2][16][HSTR];   // h (fp16) in frag-permuted order
    __shared__ float psum[2][16][8];

    const int tid = threadIdx.x, wid = tid >> 5, lane = tid & 31;
    const int q = lane & 3, r = lane >> 2;
    const int dir = blockIdx.x & 1;
    const int b0 = (blockIdx.x >> 1) * 16;

    const float* Whh = dir ? Whh_b : Whh_f;
    const float* Wih = dir ? Wih_b : Wih_f;
    const float* bih = dir ? bih_b : bih_f;
    const float* bhh = dir ? bhh_b : bhh_f;

    for (int i = tid; i < 2 * 16 * HSTR; i += NTH) (&hs[0][0][0])[i] = __float2half(0.f);

    // ---- B fragments (Whh^T), exact-W hi/lo: ks 0-3 = Whi, ks 4-7 = Wlo ----
    uint32_t bf[8][4][2];
    {
        const int qp = r >> 1, odd = r & 1;
        #pragma unroll
        for (int nt = 0; nt < 4; ++nt) {
            const int unit = 8 * wid + (nt >= 2 ? 4 : 0) + qp;
            const int row = ((nt & 1) ? (odd ? 192 : 64) : (odd ? 128 : 0)) + unit;
            const float* wr = Whh + row * 64;
            #pragma unroll
            for (int ks = 0; ks < 8; ++ks) {
                const bool lo = ks >= 4;
                const int wcol = (lo ? (ks - 4) : ks) * 16 + q * 2;
                bf[ks][nt][0] = pack2(wsplit(__ldg(wr + wcol),     lo),
                                      wsplit(__ldg(wr + wcol + 1), lo));
                bf[ks][nt][1] = pack2(wsplit(__ldg(wr + wcol + 8), lo),
                                      wsplit(__ldg(wr + wcol + 9), lo));
            }
        }
    }

    // gate-owner: units u1 = 8*wid+q, u2 = u1+4; streams r, r+8
    const int u1 = 8 * wid + q, u2 = u1 + 4;
    const float wi_i1 = Wih[u1], wi_f1 = Wih[64 + u1], wi_g1 = Wih[128 + u1], wi_o1 = Wih[192 + u1];
    const float wi_i2 = Wih[u2], wi_f2 = Wih[64 + u2], wi_g2 = Wih[128 + u2], wi_o2 = Wih[192 + u2];
    const float bi1 = bih[u1] + bhh[u1],             bf1 = bih[64 + u1] + bhh[64 + u1];
    const float bg1 = bih[128 + u1] + bhh[128 + u1], bo1 = bih[192 + u1] + bhh[192 + u1];
    const float bi2 = bih[u2] + bhh[u2],             bf2 = bih[64 + u2] + bhh[64 + u2];
    const float bg2 = bih[128 + u2] + bhh[128 + u2], bo2 = bih[192 + u2] + bhh[192 + u2];
    const float fcw1 = fc_w[dir * 64 + u1], fcw2 = fc_w[dir * 64 + u2];
    const int pc1 = perm64(u1), pc2 = perm64(u2);

    float cc[4] = {0.f, 0.f, 0.f, 0.f};
    __syncthreads();

    for (int t = 0; t < T_LEN; ++t) {
        // flush previous step's fc partials
        if (t > 0 && wid == 0 && lane < 16) {
            const float* ps = &psum[(t - 1) & 1][lane][0];
            float s = 0.f;
            #pragma unroll
            for (int j = 0; j < 8; ++j) s += ps[j];
            atomicAdd(out + (size_t)(b0 + lane) * T_LEN + (t - 1), s);
        }

        const int xt = dir ? (T_LEN - 1 - t) : t;
        const float xv0 = __ldg(x + (size_t)(b0 + r) * T_LEN + xt);
        const float xv1 = __ldg(x + (size_t)(b0 + r + 8) * T_LEN + xt);

        // ---- A fragments: 4x LDS.128 from permuted buffer ----
        const __half* hb = &hs[(t & 1) ^ 1][0][0];
        uint32_t af[4][4];
        {
            const uint4* p0 = (const uint4*)(hb + r * HSTR + q * 16);
            const uint4* p1 = (const uint4*)(hb + (r + 8) * HSTR + q * 16);
            #pragma unroll
            for (int m = 0; m < 2; ++m) {
                const uint4 v = p0[m];
                af[2*m][0] = v.x; af[2*m][2] = v.y; af[2*m+1][0] = v.z; af[2*m+1][2] = v.w;
                const uint4 u = p1[m];
                af[2*m][1] = u.x; af[2*m][3] = u.y; af[2*m+1][1] = u.z; af[2*m+1][3] = u.w;
            }
        }

        __half* hw = &hs[t & 1][0][0];
        float hval[4];

        // ---- u1: 16 HMMA (nt 0,1) then gates (MUFU overlaps u2's HMMAs below) ----
        float d[4][4] = {{0.f,0.f,0.f,0.f},{0.f,0.f,0.f,0.f},{0.f,0.f,0.f,0.f},{0.f,0.f,0.f,0.f}};
        #pragma unroll
        for (int ks = 0; ks < 8; ++ks) {
            mma16816(d[0], af[ks & 3], bf[ks][0]);
            mma16816(d[1], af[ks & 3], bf[ks][1]);
        }
        #pragma unroll
        for (int cidx = 0; cidx < 2; ++cidx) {
            const int co = cidx * 2;
            const float xv = cidx ? xv1 : xv0;
            const float zi = d[0][co]     + fmaf(xv, wi_i1, bi1);
            const float zg = d[0][co + 1] + fmaf(xv, wi_g1, bg1);
            const float zf = d[1][co]     + fmaf(xv, wi_f1, bf1);
            const float zo = d[1][co + 1] + fmaf(xv, wi_o1, bo1);
            cc[cidx] = fmaf(fsig(zf), cc[cidx], fsig(zi) * tanhapx(zg));
            hval[cidx] = fsig(zo) * tanhapx(cc[cidx]);
            hw[(cidx ? (r + 8) : r) * HSTR + pc1] = __float2half_rn(hval[cidx]);
        }

        // ---- u2: 16 HMMA (nt 2,3) then gates ----
        #pragma unroll
        for (int ks = 0; ks < 8; ++ks) {
            mma16816(d[2], af[ks & 3], bf[ks][2]);
            mma16816(d[3], af[ks & 3], bf[ks][3]);
        }
        #pragma unroll
        for (int cidx = 2; cidx < 4; ++cidx) {
            const int co = (cidx & 1) * 2;
            const float xv = (cidx & 1) ? xv1 : xv0;
            const float zi = d[2][co]     + fmaf(xv, wi_i2, bi2);
            const float zg = d[2][co + 1] + fmaf(xv, wi_g2, bg2);
            const float zf = d[3][co]     + fmaf(xv, wi_f2, bf2);
            const float zo = d[3][co + 1] + fmaf(xv, wi_o2, bo2);
            cc[cidx] = fmaf(fsig(zf), cc[cidx], fsig(zi) * tanhapx(zg));
            hval[cidx] = fsig(zo) * tanhapx(cc[cidx]);
            hw[((cidx & 1) ? (r + 8) : r) * HSTR + pc2] = __float2half_rn(hval[cidx]);
        }

        // ---- fc partials ----
        float pr  = fcw1 * hval[0] + fcw2 * hval[2];
        float pr8 = fcw1 * hval[1] + fcw2 * hval[3];
        pr  += __shfl_xor_sync(0xffffffffu, pr, 1);
        pr  += __shfl_xor_sync(0xffffffffu, pr, 2);
        pr8 += __shfl_xor_sync(0xffffffffu, pr8, 1);
        pr8 += __shfl_xor_sync(0xffffffffu, pr8, 2);
        if (q == 0) {
            psum[t & 1][r][wid] = pr;
            psum[t & 1][r + 8][wid] = pr8;
        }
        __syncthreads();
    }

    // final flush
    if (wid == 0 && lane < 16) {
        const float* ps = &psum[(T_LEN - 1) & 1][lane][0];
        float s = 0.f;
        #pragma unroll
        for (int j = 0; j < 8; ++j) s += ps[j];
        atomicAdd(out + (size_t)(b0 + lane) * T_LEN + (T_LEN - 1), s);
    }
}

extern "C" void kernel_launch(void* const* d_in, const int* in_sizes, int n_in,
                              void* d_out, int out_size) {
    const float* x     = (const float*)d_in[0];
    const float* Wih_f = (const float*)d_in[1];
    const float* Whh_f = (const float*)d_in[2];
    const float* bih_f = (const float*)d_in[3];
    const float* bhh_f = (const float*)d_in[4];
    const float* Wih_b = (const float*)d_in[5];
    const float* Whh_b = (const float*)d_in[6];
    const float* bih_b = (const float*)d_in[7];
    const float* bhh_b = (const float*)d_in[8];
    const float* fc_w  = (const float*)d_in[9];
    const float* fc_b  = (const float*)d_in[10];
    float* out = (float*)d_out;

    out_init<<<(out_size + 255) / 256, 256>>>(out, fc_b, out_size);

    const int B = in_sizes[0] / T_LEN;   // 1024
    const int grid = (B / 16) * 2;       // 128 CTAs: (batch-group, direction)
    bilstm_mma<<<grid, NTH>>>(x, Wih_f, Whh_f, bih_f, bhh_f,
                              Wih_b, Whh_b, bih_b, bhh_b, fc_w, out);
    (void)n_in;
}

// round 12
// speedup vs baseline: 2.0910x; 1.1500x over previous
#include <cuda_runtime.h>
#include <cuda_fp16.h>
#include <cstdint>

#define T_LEN 1024
#define NTH   256
#define HSTR  72         // halves per row (144 B = 9*16B): 16B-aligned, conflict-free

static __device__ __forceinline__ float tanhapx(float x) {
    float y;
    asm("tanh.approx.f32 %0, %1;" : "=f"(y) : "f"(x));
    return y;
}
static __device__ __forceinline__ float fsig(float x) {
    return fmaf(0.5f, tanhapx(0.5f * x), 0.5f);
}
static __device__ __forceinline__ uint32_t pack2(float a, float b) {
    __half2 t = __halves2half2(__float2half_rn(a), __float2half_rn(b));
    return *(uint32_t*)&t;
}
// 64-col permutation: h col c -> fragment-vectorized position
static __device__ __forceinline__ int perm64(int c) {
    return (((c & 7) >> 1) << 4) + ((c >> 4) << 2) + (((c >> 3) & 1) << 1) + (c & 1);
}
static __device__ __forceinline__ void mma16816(float* d, const uint32_t* a, const uint32_t* b) {
    asm volatile(
        "mma.sync.aligned.m16n8k16.row.col.f32.f16.f16.f32 "
        "{%0,%1,%2,%3}, {%4,%5,%6,%7}, {%8,%9}, {%0,%1,%2,%3};"
        : "+f"(d[0]), "+f"(d[1]), "+f"(d[2]), "+f"(d[3])
        : "r"(a[0]), "r"(a[1]), "r"(a[2]), "r"(a[3]), "r"(b[0]), "r"(b[1]));
}

__global__ void out_init(float* out, const float* fc_b, int n) {
    int i = blockIdx.x * blockDim.x + threadIdx.x;
    if (i < n) out[i] = fc_b[0];
}

__global__ __launch_bounds__(NTH, 1)
void bilstm_mma(const float* __restrict__ x,
                const float* __restrict__ Wih_f, const float* __restrict__ Whh_f,
                const float* __restrict__ bih_f, const float* __restrict__ bhh_f,
                const float* __restrict__ Wih_b, const float* __restrict__ Whh_b,
                const float* __restrict__ bih_b, const float* __restrict__ bhh_b,
                const float* __restrict__ fc_w, float* __restrict__ out)
{
    __shared__ __align__(16) __half hs[2][16][HSTR];   // h (fp16) in frag-permuted order
    __shared__ float psum[2][16][8];

    const int tid = threadIdx.x, wid = tid >> 5, lane = tid & 31;
    const int q = lane & 3, r = lane >> 2;
    const int dir = blockIdx.x & 1;
    const int b0 = (blockIdx.x >> 1) * 16;

    const float* Whh = dir ? Whh_b : Whh_f;
    const float* Wih = dir ? Wih_b : Wih_f;
    const float* bih = dir ? bih_b : bih_f;
    const float* bhh = dir ? bhh_b : bhh_f;

    for (int i = tid; i < 2 * 16 * HSTR; i += NTH) (&hs[0][0][0])[i] = __float2half(0.f);

    // ---- B fragments (Whh^T), pure fp16 W: bf[ks 0..3][nt 0..3][2] ----
    uint32_t bf[4][4][2];
    {
        const int qp = r >> 1, odd = r & 1;
        #pragma unroll
        for (int nt = 0; nt < 4; ++nt) {
            const int unit = 8 * wid + (nt >= 2 ? 4 : 0) + qp;
            const int row = ((nt & 1) ? (odd ? 192 : 64) : (odd ? 128 : 0)) + unit;
            const float* wr = Whh + row * 64;
            #pragma unroll
            for (int ks = 0; ks < 4; ++ks) {
                const int wcol = ks * 16 + q * 2;
                bf[ks][nt][0] = pack2(__ldg(wr + wcol),     __ldg(wr + wcol + 1));
                bf[ks][nt][1] = pack2(__ldg(wr + wcol + 8), __ldg(wr + wcol + 9));
            }
        }
    }

    // gate-owner: units u1 = 8*wid+q, u2 = u1+4; streams r, r+8
    const int u1 = 8 * wid + q, u2 = u1 + 4;
    const float wi_i1 = Wih[u1], wi_f1 = Wih[64 + u1], wi_g1 = Wih[128 + u1], wi_o1 = Wih[192 + u1];
    const float wi_i2 = Wih[u2], wi_f2 = Wih[64 + u2], wi_g2 = Wih[128 + u2], wi_o2 = Wih[192 + u2];
    const float bi1 = bih[u1] + bhh[u1],             bf1 = bih[64 + u1] + bhh[64 + u1];
    const float bg1 = bih[128 + u1] + bhh[128 + u1], bo1 = bih[192 + u1] + bhh[192 + u1];
    const float bi2 = bih[u2] + bhh[u2],             bf2 = bih[64 + u2] + bhh[64 + u2];
    const float bg2 = bih[128 + u2] + bhh[128 + u2], bo2 = bih[192 + u2] + bhh[192 + u2];
    const float fcw1 = fc_w[dir * 64 + u1], fcw2 = fc_w[dir * 64 + u2];
    const int pc1 = perm64(u1), pc2 = perm64(u2);

    float cc[4] = {0.f, 0.f, 0.f, 0.f};
    __syncthreads();

    for (int t = 0; t < T_LEN; ++t) {
        // flush previous step's fc partials
        if (t > 0 && wid == 0 && lane < 16) {
            const float* ps = &psum[(t - 1) & 1][lane][0];
            float s = 0.f;
            #pragma unroll
            for (int j = 0; j < 8; ++j) s += ps[j];
            atomicAdd(out + (size_t)(b0 + lane) * T_LEN + (t - 1), s);
        }

        const int xt = dir ? (T_LEN - 1 - t) : t;
        const float xv0 = __ldg(x + (size_t)(b0 + r) * T_LEN + xt);
        const float xv1 = __ldg(x + (size_t)(b0 + r + 8) * T_LEN + xt);

        // ---- A fragments: 4x LDS.128 from permuted buffer ----
        const __half* hb = &hs[(t & 1) ^ 1][0][0];
        uint32_t af[4][4];
        {
            const uint4* p0 = (const uint4*)(hb + r * HSTR + q * 16);
            const uint4* p1 = (const uint4*)(hb + (r + 8) * HSTR + q * 16);
            #pragma unroll
            for (int m = 0; m < 2; ++m) {
                const uint4 v = p0[m];
                af[2*m][0] = v.x; af[2*m][2] = v.y; af[2*m+1][0] = v.z; af[2*m+1][2] = v.w;
                const uint4 u = p1[m];
                af[2*m][1] = u.x; af[2*m][3] = u.y; af[2*m+1][1] = u.z; af[2*m+1][3] = u.w;
            }
        }

        __half* hw = &hs[t & 1][0][0];
        float hval[4];

        // ---- u1: 8 HMMA (nt 0,1) then gates (MUFU overlaps u2's HMMAs below) ----
        float d[4][4] = {{0.f,0.f,0.f,0.f},{0.f,0.f,0.f,0.f},{0.f,0.f,0.f,0.f},{0.f,0.f,0.f,0.f}};
        #pragma unroll
        for (int ks = 0; ks < 4; ++ks) {
            mma16816(d[0], af[ks], bf[ks][0]);
            mma16816(d[1], af[ks], bf[ks][1]);
        }
        #pragma unroll
        for (int cidx = 0; cidx < 2; ++cidx) {
            const int co = cidx * 2;
            const float xv = cidx ? xv1 : xv0;
            const float zi = d[0][co]     + fmaf(xv, wi_i1, bi1);
            const float zg = d[0][co + 1] + fmaf(xv, wi_g1, bg1);
            const float zf = d[1][co]     + fmaf(xv, wi_f1, bf1);
            const float zo = d[1][co + 1] + fmaf(xv, wi_o1, bo1);
            cc[cidx] = fmaf(fsig(zf), cc[cidx], fsig(zi) * tanhapx(zg));
            hval[cidx] = fsig(zo) * tanhapx(cc[cidx]);
            hw[(cidx ? (r + 8) : r) * HSTR + pc1] = __float2half_rn(hval[cidx]);
        }

        // ---- u2: 8 HMMA (nt 2,3) then gates ----
        #pragma unroll
        for (int ks = 0; ks < 4; ++ks) {
            mma16816(d[2], af[ks], bf[ks][2]);
            mma16816(d[3], af[ks], bf[ks][3]);
        }
        #pragma unroll
        for (int cidx = 2; cidx < 4; ++cidx) {
            const int co = (cidx & 1) * 2;
            const float xv = (cidx & 1) ? xv1 : xv0;
            const float zi = d[2][co]     + fmaf(xv, wi_i2, bi2);
            const float zg = d[2][co + 1] + fmaf(xv, wi_g2, bg2);
            const float zf = d[3][co]     + fmaf(xv, wi_f2, bf2);
            const float zo = d[3][co + 1] + fmaf(xv, wi_o2, bo2);
            cc[cidx] = fmaf(fsig(zf), cc[cidx], fsig(zi) * tanhapx(zg));
            hval[cidx] = fsig(zo) * tanhapx(cc[cidx]);
            hw[((cidx & 1) ? (r + 8) : r) * HSTR + pc2] = __float2half_rn(hval[cidx]);
        }

        // ---- fc partials ----
        float pr  = fcw1 * hval[0] + fcw2 * hval[2];
        float pr8 = fcw1 * hval[1] + fcw2 * hval[3];
        pr  += __shfl_xor_sync(0xffffffffu, pr, 1);
        pr  += __shfl_xor_sync(0xffffffffu, pr, 2);
        pr8 += __shfl_xor_sync(0xffffffffu, pr8, 1);
        pr8 += __shfl_xor_sync(0xffffffffu, pr8, 2);
        if (q == 0) {
            psum[t & 1][r][wid] = pr;
            psum[t & 1][r + 8][wid] = pr8;
        }
        __syncthreads();
    }

    // final flush
    if (wid == 0 && lane < 16) {
        const float* ps = &psum[(T_LEN - 1) & 1][lane][0];
        float s = 0.f;
        #pragma unroll
        for (int j = 0; j < 8; ++j) s += ps[j];
        atomicAdd(out + (size_t)(b0 + lane) * T_LEN + (T_LEN - 1), s);
    }
}

extern "C" void kernel_launch(void* const* d_in, const int* in_sizes, int n_in,
                              void* d_out, int out_size) {
    const float* x     = (const float*)d_in[0];
    const float* Wih_f = (const float*)d_in[1];
    const float* Whh_f = (const float*)d_in[2];
    const float* bih_f = (const float*)d_in[3];
    const float* bhh_f = (const float*)d_in[4];
    const float* Wih_b = (const float*)d_in[5];
    const float* Whh_b = (const float*)d_in[6];
    const float* bih_b = (const float*)d_in[7];
    const float* bhh_b = (const float*)d_in[8];
    const float* fc_w  = (const float*)d_in[9];
    const float* fc_b  = (const float*)d_in[10];
    float* out = (float*)d_out;

    out_init<<<(out_size + 255) / 256, 256>>>(out, fc_b, out_size);

    const int B = in_sizes[0] / T_LEN;   // 1024
    const int grid = (B / 16) * 2;       // 128 CTAs: (batch-group, direction)
    bilstm_mma<<<grid, NTH>>>(x, Wih_f, Whh_f, bih_f, bhh_f,
                              Wih_b, Whh_b, bih_b, bhh_b, fc_w, out);
    (void)n_in;
}